// round 14
// baseline (speedup 1.0000x reference)
#include <cuda_runtime.h>
#include <cuda_bf16.h>
#include <cstdint>

#define B_SZ   2
#define T_SEQ  2048
#define NH     16
#define DH     64
#define DM     1024
#define M_TOK  (B_SZ * T_SEQ)   // 4096

// ---------------------------------------------------------------------------
// Scratch (__device__ globals: allocation-free rule)
// ---------------------------------------------------------------------------
__device__ float g_AO  [M_TOK * DM];     // attention output (fp32)
// bf16 hi/lo split planes for attention
__device__ __nv_bfloat16 g_Qh [M_TOK * DM];
__device__ __nv_bfloat16 g_Ql [M_TOK * DM];
__device__ __nv_bfloat16 g_Kh [M_TOK * DM];
__device__ __nv_bfloat16 g_Kl [M_TOK * DM];
__device__ __nv_bfloat16 g_Vth[B_SZ * NH * DH * T_SEQ];   // V^T hi [bh][d][T]
__device__ __nv_bfloat16 g_Vtl[B_SZ * NH * DH * T_SEQ];   // V^T lo

// ---------------------------------------------------------------------------
// helpers
// ---------------------------------------------------------------------------
__device__ __forceinline__ uint32_t pk2(float e0, float e1) {
    uint32_t d;
    asm("cvt.rn.bf16x2.f32 %0, %1, %2;" : "=r"(d) : "f"(e1), "f"(e0));
    return d;
}
__device__ __forceinline__ float bflo(uint32_t p) { return __uint_as_float(p << 16); }
__device__ __forceinline__ float bfhi(uint32_t p) { return __uint_as_float(p & 0xffff0000u); }
// in-register tf32 round-to-nearest (bits in, bits out)
__device__ __forceinline__ void rna_r(uint32_t& x) {
    asm("cvt.rna.tf32.f32 %0, %1;" : "+r"(x) : "f"(__uint_as_float(x)));
}

// ---------------------------------------------------------------------------
// PTX wrappers
// ---------------------------------------------------------------------------
#define SW128(x) ((x) ^ (((x) >> 3) & 0x70))

__device__ __forceinline__ uint32_t s2u(const void* p) {
    uint32_t a;
    asm("{ .reg .u64 t; cvta.to.shared.u64 t, %1; cvt.u32.u64 %0, t; }"
        : "=r"(a) : "l"(p));
    return a;
}
__device__ __forceinline__ void ldsm_x4(
    uint32_t& r0, uint32_t& r1, uint32_t& r2, uint32_t& r3, uint32_t addr)
{
    asm volatile("ldmatrix.sync.aligned.m8n8.x4.shared.b16 {%0,%1,%2,%3}, [%4];"
                 : "=r"(r0), "=r"(r1), "=r"(r2), "=r"(r3) : "r"(addr));
}
__device__ __forceinline__ void mma_tf32(
    float* d, const uint32_t* a, uint32_t b0, uint32_t b1)
{
    asm volatile(
        "mma.sync.aligned.m16n8k8.row.col.f32.tf32.tf32.f32 "
        "{%0,%1,%2,%3}, {%4,%5,%6,%7}, {%8,%9}, {%0,%1,%2,%3};"
        : "+f"(d[0]), "+f"(d[1]), "+f"(d[2]), "+f"(d[3])
        : "r"(a[0]), "r"(a[1]), "r"(a[2]), "r"(a[3]), "r"(b0), "r"(b1));
}
__device__ __forceinline__ void mma_bf16(
    float* d, const uint32_t* a, uint32_t b0, uint32_t b1)
{
    asm volatile(
        "mma.sync.aligned.m16n8k16.row.col.f32.bf16.bf16.f32 "
        "{%0,%1,%2,%3}, {%4,%5,%6,%7}, {%8,%9}, {%0,%1,%2,%3};"
        : "+f"(d[0]), "+f"(d[1]), "+f"(d[2]), "+f"(d[3])
        : "r"(a[0]), "r"(a[1]), "r"(a[2]), "r"(a[3]), "r"(b0), "r"(b1));
}
__device__ __forceinline__ void cpa16(uint32_t dst, const void* src) {
    asm volatile("cp.async.cg.shared.global [%0], [%1], 16;"
                 :: "r"(dst), "l"(src));
}

// ---------------------------------------------------------------------------
// mma.sync tf32 NT GEMM, 2 CTAs/SM, one barrier per chunk. tf32-RN rounding
// applied IN-REGISTER to fragments after ldmatrix (bit-identical to the old
// memory pre-rounding; RNA is idempotent). mode 1 = QKV fused epilogue,
// mode 0 = plain fp32 C.
// ---------------------------------------------------------------------------
#define STAGE_BYTES 32768
#define GEMM_DYN_SMEM (3 * STAGE_BYTES)

__global__ __launch_bounds__(256, 2) void gemm_mma(
    const float* __restrict__ A, const float* __restrict__ Bm,
    float* __restrict__ C0, float* __restrict__ C1, float* __restrict__ C2,
    uint32_t* __restrict__ Qh, uint32_t* __restrict__ Ql,
    uint32_t* __restrict__ Kh, uint32_t* __restrict__ Kl,
    int nchunk, int mode)
{
    extern __shared__ char dsm[];
    const uint32_t smem0 = s2u(dsm);

    const int tid  = threadIdx.x;
    const int wid  = tid >> 5;
    const int lane = tid & 31;

    const int bm = blockIdx.y * 128;
    const int bn = blockIdx.x * 128;
    const int seg = bn >> 10;
    float* C = (seg == 0) ? C0 : ((seg == 1) ? C1 : C2);
    const int cn = bn & 1023;

    const int lr = tid >> 1;
    const int lb = (tid & 1) * 64;
    const float* gA = A  + (size_t)(bm + lr) * DM + (lb >> 2);
    const float* gB = Bm + (size_t)(bn + lr) * DM + (lb >> 2);

    const int wm = (wid >> 1) * 32;
    const int wn = (wid & 1) * 64;
    const int g  = lane >> 3;
    const int r  = lane & 7;

    uint32_t a_row[2], a_kb = (uint32_t)((g >> 1) * 16);
#pragma unroll
    for (int mt = 0; mt < 2; ++mt) {
        int row = wm + mt * 16 + (g & 1) * 8 + r;
        a_row[mt] = (uint32_t)SW128(row * 128);
    }
    uint32_t b_row[4], b_kb = (uint32_t)((g & 1) * 16);
#pragma unroll
    for (int p = 0; p < 4; ++p) {
        int row = wn + p * 16 + (g >> 1) * 8 + r;
        b_row[p] = (uint32_t)(16384 + SW128(row * 128));
    }

    float acc[2][8][4];
#pragma unroll
    for (int mt = 0; mt < 2; ++mt)
#pragma unroll
        for (int nt = 0; nt < 8; ++nt)
#pragma unroll
            for (int q = 0; q < 4; ++q) acc[mt][nt][q] = 0.0f;

    auto issue = [&](int c) {
        uint32_t sb = smem0 + (uint32_t)(c % 3) * STAGE_BYTES;
        const float* sa = gA + c * 32;
        const float* sbp = gB + c * 32;
#pragma unroll
        for (int i = 0; i < 4; ++i) {
            cpa16(sb + SW128(lr * 128 + lb + i * 16), sa + i * 4);
            cpa16(sb + 16384 + SW128(lr * 128 + lb + i * 16), sbp + i * 4);
        }
    };

    issue(0); asm volatile("cp.async.commit_group;" ::: "memory");
    if (nchunk > 1) issue(1);
    asm volatile("cp.async.commit_group;" ::: "memory");

    for (int c = 0; c < nchunk; ++c) {
        asm volatile("cp.async.wait_group 1;" ::: "memory");
        __syncthreads();
        if (c + 2 < nchunk) issue(c + 2);
        asm volatile("cp.async.commit_group;" ::: "memory");

        const uint32_t st = smem0 + (uint32_t)(c % 3) * STAGE_BYTES;
#pragma unroll
        for (int ks = 0; ks < 4; ++ks) {
            const uint32_t kbase = (uint32_t)(ks * 32);
            uint32_t af[2][4];
#pragma unroll
            for (int mt = 0; mt < 2; ++mt) {
                ldsm_x4(af[mt][0], af[mt][1], af[mt][2], af[mt][3],
                        (st + a_row[mt]) ^ (kbase + a_kb));
                rna_r(af[mt][0]); rna_r(af[mt][1]);
                rna_r(af[mt][2]); rna_r(af[mt][3]);
            }
            uint32_t bq[4][4];
#pragma unroll
            for (int p = 0; p < 4; ++p) {
                ldsm_x4(bq[p][0], bq[p][1], bq[p][2], bq[p][3],
                        (st + b_row[p]) ^ (kbase + b_kb));
                rna_r(bq[p][0]); rna_r(bq[p][1]);
                rna_r(bq[p][2]); rna_r(bq[p][3]);
            }
#pragma unroll
            for (int mt = 0; mt < 2; ++mt)
#pragma unroll
                for (int nt = 0; nt < 8; ++nt) {
                    const uint32_t* q = bq[nt >> 1];
                    if (nt & 1) mma_tf32(acc[mt][nt], af[mt], q[2], q[3]);
                    else        mma_tf32(acc[mt][nt], af[mt], q[0], q[1]);
                }
        }
    }

    const int erow = lane >> 2;
    const int ecol = (lane & 3) * 2;
    const bool planes = (mode == 1) && (seg < 2);
    uint32_t* PH = (seg == 0) ? Qh : Kh;
    uint32_t* PL = (seg == 0) ? Ql : Kl;
#pragma unroll
    for (int mt = 0; mt < 2; ++mt) {
#pragma unroll
        for (int half = 0; half < 2; ++half) {
            int m = bm + wm + mt * 16 + half * 8 + erow;
            size_t rowoff = (size_t)m * 1024 + cn + wn;
#pragma unroll
            for (int nt = 0; nt < 8; ++nt) {
                float vx = acc[mt][nt][half * 2 + 0];
                float vy = acc[mt][nt][half * 2 + 1];
                if (planes) {
                    size_t w = (rowoff + nt * 8 + ecol) >> 1;
                    uint32_t hw = pk2(vx, vy);
                    PH[w] = hw;
                    PL[w] = pk2(vx - bflo(hw), vy - bfhi(hw));
                    if (seg == 0) continue;     // q: planes only
                }
                *(float2*)(C + rowoff + nt * 8 + ecol) = make_float2(vx, vy);
            }
        }
    }
}

// ---------------------------------------------------------------------------
// V transpose + bf16 split: vout [tok][h][64] -> Vth/Vtl [bh][d][T]
// ---------------------------------------------------------------------------
__global__ __launch_bounds__(256) void transpose_v(const float* __restrict__ V)
{
    __shared__ float tile[32][33];
    const int t0 = blockIdx.x * 32;
    const int d0 = blockIdx.y * 32;
    const int bh = blockIdx.z;
    const int b = bh >> 4, h = bh & 15;
    const int tx = threadIdx.x, ty = threadIdx.y;

#pragma unroll
    for (int i = 0; i < 4; ++i) {
        int t = t0 + ty + i * 8;
        tile[ty + i * 8][tx] =
            V[((size_t)(b * T_SEQ + t) * NH + h) * DH + d0 + tx];
    }
    __syncthreads();
#pragma unroll
    for (int i = 0; i < 4; ++i) {
        int d = d0 + ty + i * 8;
        float val = tile[tx][ty + i * 8];
        size_t o = ((size_t)bh * DH + d) * T_SEQ + t0 + tx;
        __nv_bfloat16 hb = __float2bfloat16_rn(val);
        g_Vth[o] = hb;
        g_Vtl[o] = __float2bfloat16_rn(val - __bfloat162float(hb));
    }
}

// ---------------------------------------------------------------------------
// bf16x2-split flash attention (kv 128, 160KB, 1 CTA/SM), single barrier per
// kv tile. Epilogue stores raw fp32 (the O-GEMM rounds in-register; RNA is
// idempotent so numerics are unchanged).
// ---------------------------------------------------------------------------
#define ATTN_DYN_SMEM (32768 + 65536 + 65536)

__global__ __launch_bounds__(256, 1) void attn_tc()
{
    extern __shared__ char dsm[];
    const uint32_t sQh = s2u(dsm);
    const uint32_t sQl = sQh + 16384;
    const uint32_t sK0 = sQh + 32768;
    const uint32_t sV0 = sQh + 98304;

    const int tid  = threadIdx.x;
    const int lane = tid & 31;
    const int warp = tid >> 5;
    const int qt   = 15 - (int)blockIdx.x;
    const int bh   = blockIdx.y;
    const int b    = bh >> 4, h = bh & 15;

    const int g = lane >> 3, r = lane & 7;

    const int krow = tid >> 1, kc = tid & 1;
    const int vd = tid >> 2, vp = tid & 3;

    {
        size_t off = ((size_t)(b * T_SEQ + qt * 128 + krow) * NH + h) * DH + kc * 32;
        const __nv_bfloat16* qh = g_Qh + off;
        const __nv_bfloat16* ql = g_Ql + off;
#pragma unroll
        for (int i = 0; i < 4; ++i) {
            uint32_t d = SW128(krow * 128 + kc * 64 + i * 16);
            cpa16(sQh + d, qh + i * 8);
            cpa16(sQl + d, ql + i * 8);
        }
    }
    auto issueKV = [&](int j, int s) {
        size_t koff = ((size_t)(b * T_SEQ + j * 128 + krow) * NH + h) * DH + kc * 32;
        uint32_t kb = sK0 + s * 32768;
#pragma unroll
        for (int i = 0; i < 4; ++i) {
            uint32_t d = SW128(krow * 128 + kc * 64 + i * 16);
            cpa16(kb + d,         g_Kh + koff + i * 8);
            cpa16(kb + 16384 + d, g_Kl + koff + i * 8);
        }
        size_t voff = ((size_t)bh * DH + vd) * T_SEQ + j * 128 + vp * 32;
        uint32_t vb = sV0 + s * 32768 + (vp >> 1) * 8192;
#pragma unroll
        for (int i = 0; i < 4; ++i) {
            uint32_t d = SW128(vd * 128 + (vp & 1) * 64 + i * 16);
            cpa16(vb + d,         g_Vth + voff + i * 8);
            cpa16(vb + 16384 + d, g_Vtl + voff + i * 8);
        }
    };

    issueKV(0, 0);
    asm volatile("cp.async.commit_group;" ::: "memory");

    const uint32_t aro = (uint32_t)SW128((warp * 16 + (g & 1) * 8 + r) * 128);
    const uint32_t kA  = (uint32_t)((g >> 1) * 16);
    uint32_t bro[4];
#pragma unroll
    for (int p = 0; p < 4; ++p)
        bro[p] = (uint32_t)SW128((p * 16 + (g >> 1) * 8 + r) * 128);
    const uint32_t kB = (uint32_t)((g & 1) * 16);

    float acc_o[8][4];
#pragma unroll
    for (int nt = 0; nt < 8; ++nt)
#pragma unroll
        for (int q = 0; q < 4; ++q) acc_o[nt][q] = 0.0f;
    float m0 = -1e30f, m1 = -1e30f, ls0 = 0.0f, ls1 = 0.0f;

    const int qrow0 = warp * 16 + (lane >> 2);

    for (int j = 0; j <= qt; ++j) {
        const int s = j & 1;
        asm volatile("cp.async.wait_group 0;" ::: "memory");
        __syncthreads();
        if (j < qt) {
            issueKV(j + 1, s ^ 1);
            asm volatile("cp.async.commit_group;" ::: "memory");
        }

        const bool diag = (j == qt);
#pragma unroll
        for (int hb2 = 0; hb2 < 2; ++hb2) {
            if (diag && hb2 == 1 && warp < 4) continue;

            float acc_s[8][4];
#pragma unroll
            for (int nt = 0; nt < 8; ++nt)
#pragma unroll
                for (int q = 0; q < 4; ++q) acc_s[nt][q] = 0.0f;

            const uint32_t kbH = sK0 + s * 32768 + hb2 * 8192;
            const uint32_t kbL = kbH + 16384;
#pragma unroll
            for (int ks = 0; ks < 4; ++ks) {
                const uint32_t kx = (uint32_t)(ks * 32);
                uint32_t qh4[4], ql4[4];
                ldsm_x4(qh4[0], qh4[1], qh4[2], qh4[3], sQh + (aro ^ (kx + kA)));
                ldsm_x4(ql4[0], ql4[1], ql4[2], ql4[3], sQl + (aro ^ (kx + kA)));
                uint32_t kh4[4][4], kl4[4][4];
#pragma unroll
                for (int p = 0; p < 4; ++p) {
                    ldsm_x4(kh4[p][0], kh4[p][1], kh4[p][2], kh4[p][3],
                            kbH + (bro[p] ^ (kx + kB)));
                    ldsm_x4(kl4[p][0], kl4[p][1], kl4[p][2], kl4[p][3],
                            kbL + (bro[p] ^ (kx + kB)));
                }
#pragma unroll
                for (int nt = 0; nt < 8; ++nt) {
                    const uint32_t* bh3 = kh4[nt >> 1] + (nt & 1) * 2;
                    const uint32_t* bl3 = kl4[nt >> 1] + (nt & 1) * 2;
                    mma_bf16(acc_s[nt], qh4, bh3[0], bh3[1]);
                    mma_bf16(acc_s[nt], qh4, bl3[0], bl3[1]);
                    mma_bf16(acc_s[nt], ql4, bh3[0], bh3[1]);
                }
            }

#pragma unroll
            for (int h2 = 0; h2 < 2; ++h2) {
                const int qg = qrow0 + h2 * 8;
                float mx = -1e30f;
#pragma unroll
                for (int t = 0; t < 8; ++t)
#pragma unroll
                    for (int e = 0; e < 2; ++e) {
                        float sv = acc_s[t][h2 * 2 + e] * 0.125f;
                        if (diag) {
                            int kvl = hb2 * 64 + t * 8 + (lane & 3) * 2 + e;
                            if (kvl > qg) sv = -1e30f;
                        }
                        acc_s[t][h2 * 2 + e] = sv;
                        mx = fmaxf(mx, sv);
                    }
                mx = fmaxf(mx, __shfl_xor_sync(0xffffffffu, mx, 1));
                mx = fmaxf(mx, __shfl_xor_sync(0xffffffffu, mx, 2));
                float mold = h2 ? m1 : m0;
                float mn   = fmaxf(mold, mx);
                float corr = __expf(mold - mn);
                float lp   = 0.0f;
#pragma unroll
                for (int t = 0; t < 8; ++t)
#pragma unroll
                    for (int e = 0; e < 2; ++e) {
                        float p = __expf(acc_s[t][h2 * 2 + e] - mn);
                        acc_s[t][h2 * 2 + e] = p;
                        lp += p;
                    }
                if (h2) { m1 = mn; ls1 = ls1 * corr + lp; }
                else    { m0 = mn; ls0 = ls0 * corr + lp; }
#pragma unroll
                for (int nt = 0; nt < 8; ++nt) {
                    acc_o[nt][h2 * 2 + 0] *= corr;
                    acc_o[nt][h2 * 2 + 1] *= corr;
                }
            }

            const uint32_t vbH = sV0 + s * 32768 + hb2 * 8192;
            const uint32_t vbL = vbH + 16384;
#pragma unroll
            for (int kk = 0; kk < 4; ++kk) {
                uint32_t pah[4], pal[4];
#pragma unroll
                for (int q2 = 0; q2 < 2; ++q2) {
                    const float* cs = acc_s[2 * kk + q2];
                    uint32_t h0 = pk2(cs[0], cs[1]);
                    uint32_t h1 = pk2(cs[2], cs[3]);
                    pah[q2 * 2 + 0] = h0; pah[q2 * 2 + 1] = h1;
                    pal[q2 * 2 + 0] = pk2(cs[0] - bflo(h0), cs[1] - bfhi(h0));
                    pal[q2 * 2 + 1] = pk2(cs[2] - bflo(h1), cs[3] - bfhi(h1));
                }
                const uint32_t kx = (uint32_t)(kk * 32);
                uint32_t vh4[4][4], vl4[4][4];
#pragma unroll
                for (int p = 0; p < 4; ++p) {
                    ldsm_x4(vh4[p][0], vh4[p][1], vh4[p][2], vh4[p][3],
                            vbH + (bro[p] ^ (kx + kB)));
                    ldsm_x4(vl4[p][0], vl4[p][1], vl4[p][2], vl4[p][3],
                            vbL + (bro[p] ^ (kx + kB)));
                }
#pragma unroll
                for (int nt = 0; nt < 8; ++nt) {
                    const uint32_t* bh3 = vh4[nt >> 1] + (nt & 1) * 2;
                    const uint32_t* bl3 = vl4[nt >> 1] + (nt & 1) * 2;
                    mma_bf16(acc_o[nt], pah, bh3[0], bh3[1]);
                    mma_bf16(acc_o[nt], pah, bl3[0], bl3[1]);
                    mma_bf16(acc_o[nt], pal, bh3[0], bh3[1]);
                }
            }
        }
    }

#pragma unroll
    for (int h2 = 0; h2 < 2; ++h2) {
        float l = h2 ? ls1 : ls0;
        l += __shfl_xor_sync(0xffffffffu, l, 1);
        l += __shfl_xor_sync(0xffffffffu, l, 2);
        float inv = 1.0f / l;
        int tok = b * T_SEQ + qt * 128 + warp * 16 + h2 * 8 + (lane >> 2);
        float* dst = g_AO + ((size_t)tok * NH + h) * DH;
#pragma unroll
        for (int nt = 0; nt < 8; ++nt) {
            int d = nt * 8 + (lane & 3) * 2;
            float2 v;
            v.x = acc_o[nt][h2 * 2 + 0] * inv;
            v.y = acc_o[nt][h2 * 2 + 1] * inv;
            *(float2*)(dst + d) = v;
        }
    }
}

// ---------------------------------------------------------------------------
// Launch: GEMMs read raw inputs (tf32-RN applied in-register)
// ---------------------------------------------------------------------------
extern "C" void kernel_launch(void* const* d_in, const int* in_sizes, int n_in,
                              void* d_out, int out_size)
{
    (void)in_sizes; (void)n_in; (void)out_size;
    const float* x     = (const float*)d_in[0];
    const float* w_qkv = (const float*)d_in[1];
    const float* w_o   = (const float*)d_in[2];

    float* out  = (float*)d_out;
    float* kout = out  + (size_t)M_TOK * DM;
    float* vout = kout + (size_t)M_TOK * DM;

    float *aoptr;
    uint32_t *qh, *ql, *kh, *kl;
    cudaGetSymbolAddress((void**)&aoptr, g_AO);
    cudaGetSymbolAddress((void**)&qh,    g_Qh);
    cudaGetSymbolAddress((void**)&ql,    g_Ql);
    cudaGetSymbolAddress((void**)&kh,    g_Kh);
    cudaGetSymbolAddress((void**)&kl,    g_Kl);

    cudaFuncSetAttribute(gemm_mma, cudaFuncAttributeMaxDynamicSharedMemorySize,
                         GEMM_DYN_SMEM);
    cudaFuncSetAttribute(attn_tc, cudaFuncAttributeMaxDynamicSharedMemorySize,
                         ATTN_DYN_SMEM);

    // 1) QKV projection (fused epilogue): q -> bf16 planes, k -> kout + planes,
    //    v -> vout. Inputs rounded to tf32-RN in-register.
    gemm_mma<<<dim3(3 * DM / 128, M_TOK / 128), 256, GEMM_DYN_SMEM>>>(
        x, w_qkv, out /*dummy, unwritten*/, kout, vout, qh, ql, kh, kl,
        DM / 32, 1);

    // 2) V transpose + split
    transpose_v<<<dim3(T_SEQ / 32, DH / 32, B_SZ * NH), dim3(32, 8)>>>(vout);

    // 3) bf16x2-split tensor-core causal attention
    attn_tc<<<dim3(T_SEQ / 128, B_SZ * NH), 256, ATTN_DYN_SMEM>>>();

    // 4) output projection
    gemm_mma<<<dim3(DM / 128, M_TOK / 128), 256, GEMM_DYN_SMEM>>>(
        aoptr, w_o, out, out, out, qh, ql, kh, kl, DM / 32, 0);
}

// round 15
// speedup vs baseline: 1.0565x; 1.0565x over previous
#include <cuda_runtime.h>
#include <cuda_bf16.h>
#include <cstdint>

#define B_SZ   2
#define T_SEQ  2048
#define NH     16
#define DH     64
#define DM     1024
#define M_TOK  (B_SZ * T_SEQ)   // 4096

// ---------------------------------------------------------------------------
// Scratch (__device__ globals: allocation-free rule)
// ---------------------------------------------------------------------------
__device__ float g_AO  [M_TOK * DM];     // attention output (tf32-RN rounded)
__device__ float g_Xr  [M_TOK * DM];     // x, tf32-RN rounded
__device__ float g_Wqkv[3 * DM * DM];    // w_qkv, tf32-RN rounded
__device__ float g_Wo  [DM * DM];        // w_o, tf32-RN rounded
// bf16 hi/lo split planes for attention
__device__ __nv_bfloat16 g_Qh [M_TOK * DM];
__device__ __nv_bfloat16 g_Ql [M_TOK * DM];
__device__ __nv_bfloat16 g_Kh [M_TOK * DM];
__device__ __nv_bfloat16 g_Kl [M_TOK * DM];
__device__ __nv_bfloat16 g_Vth[B_SZ * NH * DH * T_SEQ];   // V^T hi [bh][d][T]
__device__ __nv_bfloat16 g_Vtl[B_SZ * NH * DH * T_SEQ];   // V^T lo

// ---------------------------------------------------------------------------
// helpers
// ---------------------------------------------------------------------------
__device__ __forceinline__ float tf32_rna(float x) {
    uint32_t u;
    asm("cvt.rna.tf32.f32 %0, %1;" : "=r"(u) : "f"(x));
    return __uint_as_float(u);
}
__device__ __forceinline__ uint32_t pk2(float e0, float e1) {
    uint32_t d;
    asm("cvt.rn.bf16x2.f32 %0, %1, %2;" : "=r"(d) : "f"(e1), "f"(e0));
    return d;
}
__device__ __forceinline__ float bflo(uint32_t p) { return __uint_as_float(p << 16); }
__device__ __forceinline__ float bfhi(uint32_t p) { return __uint_as_float(p & 0xffff0000u); }

// Fused tf32-RN rounding of all three fp32 inputs in ONE launch.
#define N4_X  (M_TOK * DM / 4)           // 1048576
#define N4_WQ (3 * DM * DM / 4)          //  786432
#define N4_WO (DM * DM / 4)              //  262144
#define N4_TOT (N4_X + N4_WQ + N4_WO)

__global__ __launch_bounds__(256) void round_all_kernel(
    const float4* __restrict__ x,  float4* __restrict__ xr,
    const float4* __restrict__ wq, float4* __restrict__ wqr,
    const float4* __restrict__ wo, float4* __restrict__ wor)
{
    int i = blockIdx.x * blockDim.x + threadIdx.x;
    const float4* src;
    float4* dst;
    int off;
    if (i < N4_X)               { src = x;  dst = xr;  off = i; }
    else if (i < N4_X + N4_WQ)  { src = wq; dst = wqr; off = i - N4_X; }
    else if (i < N4_TOT)        { src = wo; dst = wor; off = i - N4_X - N4_WQ; }
    else return;
    float4 v = src[off];
    v.x = tf32_rna(v.x); v.y = tf32_rna(v.y);
    v.z = tf32_rna(v.z); v.w = tf32_rna(v.w);
    dst[off] = v;
}

// ---------------------------------------------------------------------------
// PTX wrappers
// ---------------------------------------------------------------------------
#define SW128(x) ((x) ^ (((x) >> 3) & 0x70))

__device__ __forceinline__ uint32_t s2u(const void* p) {
    uint32_t a;
    asm("{ .reg .u64 t; cvta.to.shared.u64 t, %1; cvt.u32.u64 %0, t; }"
        : "=r"(a) : "l"(p));
    return a;
}
__device__ __forceinline__ void ldsm_x4(
    uint32_t& r0, uint32_t& r1, uint32_t& r2, uint32_t& r3, uint32_t addr)
{
    asm volatile("ldmatrix.sync.aligned.m8n8.x4.shared.b16 {%0,%1,%2,%3}, [%4];"
                 : "=r"(r0), "=r"(r1), "=r"(r2), "=r"(r3) : "r"(addr));
}
__device__ __forceinline__ void mma_tf32(
    float* d, const uint32_t* a, uint32_t b0, uint32_t b1)
{
    asm volatile(
        "mma.sync.aligned.m16n8k8.row.col.f32.tf32.tf32.f32 "
        "{%0,%1,%2,%3}, {%4,%5,%6,%7}, {%8,%9}, {%0,%1,%2,%3};"
        : "+f"(d[0]), "+f"(d[1]), "+f"(d[2]), "+f"(d[3])
        : "r"(a[0]), "r"(a[1]), "r"(a[2]), "r"(a[3]), "r"(b0), "r"(b1));
}
__device__ __forceinline__ void mma_bf16(
    float* d, const uint32_t* a, uint32_t b0, uint32_t b1)
{
    asm volatile(
        "mma.sync.aligned.m16n8k16.row.col.f32.bf16.bf16.f32 "
        "{%0,%1,%2,%3}, {%4,%5,%6,%7}, {%8,%9}, {%0,%1,%2,%3};"
        : "+f"(d[0]), "+f"(d[1]), "+f"(d[2]), "+f"(d[3])
        : "r"(a[0]), "r"(a[1]), "r"(a[2]), "r"(a[3]), "r"(b0), "r"(b1));
}
__device__ __forceinline__ void cpa16(uint32_t dst, const void* src) {
    asm volatile("cp.async.cg.shared.global [%0], [%1], 16;"
                 :: "r"(dst), "l"(src));
}

// ---------------------------------------------------------------------------
// mma.sync tf32 NT GEMM, 2 CTAs/SM, one barrier per chunk (R13 design,
// measured 201us QKV at healthy clocks). mode 1 = QKV fused epilogue,
// mode 0 = plain fp32 C.
// ---------------------------------------------------------------------------
#define STAGE_BYTES 32768
#define GEMM_DYN_SMEM (3 * STAGE_BYTES)

__global__ __launch_bounds__(256, 2) void gemm_mma(
    const float* __restrict__ A, const float* __restrict__ Bm,
    float* __restrict__ C0, float* __restrict__ C1, float* __restrict__ C2,
    uint32_t* __restrict__ Qh, uint32_t* __restrict__ Ql,
    uint32_t* __restrict__ Kh, uint32_t* __restrict__ Kl,
    int nchunk, int mode)
{
    extern __shared__ char dsm[];
    const uint32_t smem0 = s2u(dsm);

    const int tid  = threadIdx.x;
    const int wid  = tid >> 5;
    const int lane = tid & 31;

    const int bm = blockIdx.y * 128;
    const int bn = blockIdx.x * 128;
    const int seg = bn >> 10;
    float* C = (seg == 0) ? C0 : ((seg == 1) ? C1 : C2);
    const int cn = bn & 1023;

    const int lr = tid >> 1;
    const int lb = (tid & 1) * 64;
    const float* gA = A  + (size_t)(bm + lr) * DM + (lb >> 2);
    const float* gB = Bm + (size_t)(bn + lr) * DM + (lb >> 2);

    const int wm = (wid >> 1) * 32;
    const int wn = (wid & 1) * 64;
    const int g  = lane >> 3;
    const int r  = lane & 7;

    uint32_t a_row[2], a_kb = (uint32_t)((g >> 1) * 16);
#pragma unroll
    for (int mt = 0; mt < 2; ++mt) {
        int row = wm + mt * 16 + (g & 1) * 8 + r;
        a_row[mt] = (uint32_t)SW128(row * 128);
    }
    uint32_t b_row[4], b_kb = (uint32_t)((g & 1) * 16);
#pragma unroll
    for (int p = 0; p < 4; ++p) {
        int row = wn + p * 16 + (g >> 1) * 8 + r;
        b_row[p] = (uint32_t)(16384 + SW128(row * 128));
    }

    float acc[2][8][4];
#pragma unroll
    for (int mt = 0; mt < 2; ++mt)
#pragma unroll
        for (int nt = 0; nt < 8; ++nt)
#pragma unroll
            for (int q = 0; q < 4; ++q) acc[mt][nt][q] = 0.0f;

    auto issue = [&](int c) {
        uint32_t sb = smem0 + (uint32_t)(c % 3) * STAGE_BYTES;
        const float* sa = gA + c * 32;
        const float* sbp = gB + c * 32;
#pragma unroll
        for (int i = 0; i < 4; ++i) {
            cpa16(sb + SW128(lr * 128 + lb + i * 16), sa + i * 4);
            cpa16(sb + 16384 + SW128(lr * 128 + lb + i * 16), sbp + i * 4);
        }
    };

    issue(0); asm volatile("cp.async.commit_group;" ::: "memory");
    if (nchunk > 1) issue(1);
    asm volatile("cp.async.commit_group;" ::: "memory");

    for (int c = 0; c < nchunk; ++c) {
        asm volatile("cp.async.wait_group 1;" ::: "memory");
        __syncthreads();
        if (c + 2 < nchunk) issue(c + 2);
        asm volatile("cp.async.commit_group;" ::: "memory");

        const uint32_t st = smem0 + (uint32_t)(c % 3) * STAGE_BYTES;
#pragma unroll
        for (int ks = 0; ks < 4; ++ks) {
            const uint32_t kbase = (uint32_t)(ks * 32);
            uint32_t af[2][4];
#pragma unroll
            for (int mt = 0; mt < 2; ++mt)
                ldsm_x4(af[mt][0], af[mt][1], af[mt][2], af[mt][3],
                        (st + a_row[mt]) ^ (kbase + a_kb));
            uint32_t bq[4][4];
#pragma unroll
            for (int p = 0; p < 4; ++p)
                ldsm_x4(bq[p][0], bq[p][1], bq[p][2], bq[p][3],
                        (st + b_row[p]) ^ (kbase + b_kb));
#pragma unroll
            for (int mt = 0; mt < 2; ++mt)
#pragma unroll
                for (int nt = 0; nt < 8; ++nt) {
                    const uint32_t* q = bq[nt >> 1];
                    if (nt & 1) mma_tf32(acc[mt][nt], af[mt], q[2], q[3]);
                    else        mma_tf32(acc[mt][nt], af[mt], q[0], q[1]);
                }
        }
    }

    const int erow = lane >> 2;
    const int ecol = (lane & 3) * 2;
    const bool planes = (mode == 1) && (seg < 2);
    uint32_t* PH = (seg == 0) ? Qh : Kh;
    uint32_t* PL = (seg == 0) ? Ql : Kl;
#pragma unroll
    for (int mt = 0; mt < 2; ++mt) {
#pragma unroll
        for (int half = 0; half < 2; ++half) {
            int m = bm + wm + mt * 16 + half * 8 + erow;
            size_t rowoff = (size_t)m * 1024 + cn + wn;
#pragma unroll
            for (int nt = 0; nt < 8; ++nt) {
                float vx = acc[mt][nt][half * 2 + 0];
                float vy = acc[mt][nt][half * 2 + 1];
                if (planes) {
                    size_t w = (rowoff + nt * 8 + ecol) >> 1;
                    uint32_t hw = pk2(vx, vy);
                    PH[w] = hw;
                    PL[w] = pk2(vx - bflo(hw), vy - bfhi(hw));
                    if (seg == 0) continue;     // q: planes only
                }
                *(float2*)(C + rowoff + nt * 8 + ecol) = make_float2(vx, vy);
            }
        }
    }
}

// ---------------------------------------------------------------------------
// V transpose + bf16 split: vout [tok][h][64] -> Vth/Vtl [bh][d][T]
// ---------------------------------------------------------------------------
__global__ __launch_bounds__(256) void transpose_v(const float* __restrict__ V)
{
    __shared__ float tile[32][33];
    const int t0 = blockIdx.x * 32;
    const int d0 = blockIdx.y * 32;
    const int bh = blockIdx.z;
    const int b = bh >> 4, h = bh & 15;
    const int tx = threadIdx.x, ty = threadIdx.y;

#pragma unroll
    for (int i = 0; i < 4; ++i) {
        int t = t0 + ty + i * 8;
        tile[ty + i * 8][tx] =
            V[((size_t)(b * T_SEQ + t) * NH + h) * DH + d0 + tx];
    }
    __syncthreads();
#pragma unroll
    for (int i = 0; i < 4; ++i) {
        int d = d0 + ty + i * 8;
        float val = tile[tx][ty + i * 8];
        size_t o = ((size_t)bh * DH + d) * T_SEQ + t0 + tx;
        __nv_bfloat16 hb = __float2bfloat16_rn(val);
        g_Vth[o] = hb;
        g_Vtl[o] = __float2bfloat16_rn(val - __bfloat162float(hb));
    }
}

// ---------------------------------------------------------------------------
// bf16x2-split flash attention (kv 128, 160KB, 1 CTA/SM), single barrier per
// kv tile. Q fragments hoisted to registers (loaded once at j==0): Q is
// invariant across kv tiles, saving 16 warp-LDSM per tile.
// ---------------------------------------------------------------------------
#define ATTN_DYN_SMEM (32768 + 65536 + 65536)

__global__ __launch_bounds__(256, 1) void attn_tc()
{
    extern __shared__ char dsm[];
    const uint32_t sQh = s2u(dsm);
    const uint32_t sQl = sQh + 16384;
    const uint32_t sK0 = sQh + 32768;
    const uint32_t sV0 = sQh + 98304;

    const int tid  = threadIdx.x;
    const int lane = tid & 31;
    const int warp = tid >> 5;
    const int qt   = 15 - (int)blockIdx.x;
    const int bh   = blockIdx.y;
    const int b    = bh >> 4, h = bh & 15;

    const int g = lane >> 3, r = lane & 7;

    const int krow = tid >> 1, kc = tid & 1;
    const int vd = tid >> 2, vp = tid & 3;

    {
        size_t off = ((size_t)(b * T_SEQ + qt * 128 + krow) * NH + h) * DH + kc * 32;
        const __nv_bfloat16* qh = g_Qh + off;
        const __nv_bfloat16* ql = g_Ql + off;
#pragma unroll
        for (int i = 0; i < 4; ++i) {
            uint32_t d = SW128(krow * 128 + kc * 64 + i * 16);
            cpa16(sQh + d, qh + i * 8);
            cpa16(sQl + d, ql + i * 8);
        }
    }
    auto issueKV = [&](int j, int s) {
        size_t koff = ((size_t)(b * T_SEQ + j * 128 + krow) * NH + h) * DH + kc * 32;
        uint32_t kb = sK0 + s * 32768;
#pragma unroll
        for (int i = 0; i < 4; ++i) {
            uint32_t d = SW128(krow * 128 + kc * 64 + i * 16);
            cpa16(kb + d,         g_Kh + koff + i * 8);
            cpa16(kb + 16384 + d, g_Kl + koff + i * 8);
        }
        size_t voff = ((size_t)bh * DH + vd) * T_SEQ + j * 128 + vp * 32;
        uint32_t vb = sV0 + s * 32768 + (vp >> 1) * 8192;
#pragma unroll
        for (int i = 0; i < 4; ++i) {
            uint32_t d = SW128(vd * 128 + (vp & 1) * 64 + i * 16);
            cpa16(vb + d,         g_Vth + voff + i * 8);
            cpa16(vb + 16384 + d, g_Vtl + voff + i * 8);
        }
    };

    issueKV(0, 0);
    asm volatile("cp.async.commit_group;" ::: "memory");

    const uint32_t aro = (uint32_t)SW128((warp * 16 + (g & 1) * 8 + r) * 128);
    const uint32_t kA  = (uint32_t)((g >> 1) * 16);
    uint32_t bro[4];
#pragma unroll
    for (int p = 0; p < 4; ++p)
        bro[p] = (uint32_t)SW128((p * 16 + (g >> 1) * 8 + r) * 128);
    const uint32_t kB = (uint32_t)((g & 1) * 16);

    float acc_o[8][4];
#pragma unroll
    for (int nt = 0; nt < 8; ++nt)
#pragma unroll
        for (int q = 0; q < 4; ++q) acc_o[nt][q] = 0.0f;
    float m0 = -1e30f, m1 = -1e30f, ls0 = 0.0f, ls1 = 0.0f;

    uint32_t qfh[4][4], qfl[4][4];   // Q fragments, loaded once

    const int qrow0 = warp * 16 + (lane >> 2);

    for (int j = 0; j <= qt; ++j) {
        const int s = j & 1;
        asm volatile("cp.async.wait_group 0;" ::: "memory");
        __syncthreads();
        if (j < qt) {
            issueKV(j + 1, s ^ 1);
            asm volatile("cp.async.commit_group;" ::: "memory");
        }

        if (j == 0) {
#pragma unroll
            for (int ks = 0; ks < 4; ++ks) {
                const uint32_t kx = (uint32_t)(ks * 32);
                ldsm_x4(qfh[ks][0], qfh[ks][1], qfh[ks][2], qfh[ks][3],
                        sQh + (aro ^ (kx + kA)));
                ldsm_x4(qfl[ks][0], qfl[ks][1], qfl[ks][2], qfl[ks][3],
                        sQl + (aro ^ (kx + kA)));
            }
        }

        const bool diag = (j == qt);
#pragma unroll
        for (int hb2 = 0; hb2 < 2; ++hb2) {
            if (diag && hb2 == 1 && warp < 4) continue;

            float acc_s[8][4];
#pragma unroll
            for (int nt = 0; nt < 8; ++nt)
#pragma unroll
                for (int q = 0; q < 4; ++q) acc_s[nt][q] = 0.0f;

            const uint32_t kbH = sK0 + s * 32768 + hb2 * 8192;
            const uint32_t kbL = kbH + 16384;
#pragma unroll
            for (int ks = 0; ks < 4; ++ks) {
                const uint32_t kx = (uint32_t)(ks * 32);
                uint32_t kh4[4][4], kl4[4][4];
#pragma unroll
                for (int p = 0; p < 4; ++p) {
                    ldsm_x4(kh4[p][0], kh4[p][1], kh4[p][2], kh4[p][3],
                            kbH + (bro[p] ^ (kx + kB)));
                    ldsm_x4(kl4[p][0], kl4[p][1], kl4[p][2], kl4[p][3],
                            kbL + (bro[p] ^ (kx + kB)));
                }
#pragma unroll
                for (int nt = 0; nt < 8; ++nt) {
                    const uint32_t* bh3 = kh4[nt >> 1] + (nt & 1) * 2;
                    const uint32_t* bl3 = kl4[nt >> 1] + (nt & 1) * 2;
                    mma_bf16(acc_s[nt], qfh[ks], bh3[0], bh3[1]);
                    mma_bf16(acc_s[nt], qfh[ks], bl3[0], bl3[1]);
                    mma_bf16(acc_s[nt], qfl[ks], bh3[0], bh3[1]);
                }
            }

#pragma unroll
            for (int h2 = 0; h2 < 2; ++h2) {
                const int qg = qrow0 + h2 * 8;
                float mx = -1e30f;
#pragma unroll
                for (int t = 0; t < 8; ++t)
#pragma unroll
                    for (int e = 0; e < 2; ++e) {
                        float sv = acc_s[t][h2 * 2 + e] * 0.125f;
                        if (diag) {
                            int kvl = hb2 * 64 + t * 8 + (lane & 3) * 2 + e;
                            if (kvl > qg) sv = -1e30f;
                        }
                        acc_s[t][h2 * 2 + e] = sv;
                        mx = fmaxf(mx, sv);
                    }
                mx = fmaxf(mx, __shfl_xor_sync(0xffffffffu, mx, 1));
                mx = fmaxf(mx, __shfl_xor_sync(0xffffffffu, mx, 2));
                float mold = h2 ? m1 : m0;
                float mn   = fmaxf(mold, mx);
                float corr = __expf(mold - mn);
                float lp   = 0.0f;
#pragma unroll
                for (int t = 0; t < 8; ++t)
#pragma unroll
                    for (int e = 0; e < 2; ++e) {
                        float p = __expf(acc_s[t][h2 * 2 + e] - mn);
                        acc_s[t][h2 * 2 + e] = p;
                        lp += p;
                    }
                if (h2) { m1 = mn; ls1 = ls1 * corr + lp; }
                else    { m0 = mn; ls0 = ls0 * corr + lp; }
#pragma unroll
                for (int nt = 0; nt < 8; ++nt) {
                    acc_o[nt][h2 * 2 + 0] *= corr;
                    acc_o[nt][h2 * 2 + 1] *= corr;
                }
            }

            const uint32_t vbH = sV0 + s * 32768 + hb2 * 8192;
            const uint32_t vbL = vbH + 16384;
#pragma unroll
            for (int kk = 0; kk < 4; ++kk) {
                uint32_t pah[4], pal[4];
#pragma unroll
                for (int q2 = 0; q2 < 2; ++q2) {
                    const float* cs = acc_s[2 * kk + q2];
                    uint32_t h0 = pk2(cs[0], cs[1]);
                    uint32_t h1 = pk2(cs[2], cs[3]);
                    pah[q2 * 2 + 0] = h0; pah[q2 * 2 + 1] = h1;
                    pal[q2 * 2 + 0] = pk2(cs[0] - bflo(h0), cs[1] - bfhi(h0));
                    pal[q2 * 2 + 1] = pk2(cs[2] - bflo(h1), cs[3] - bfhi(h1));
                }
                const uint32_t kx = (uint32_t)(kk * 32);
                uint32_t vh4[4][4], vl4[4][4];
#pragma unroll
                for (int p = 0; p < 4; ++p) {
                    ldsm_x4(vh4[p][0], vh4[p][1], vh4[p][2], vh4[p][3],
                            vbH + (bro[p] ^ (kx + kB)));
                    ldsm_x4(vl4[p][0], vl4[p][1], vl4[p][2], vl4[p][3],
                            vbL + (bro[p] ^ (kx + kB)));
                }
#pragma unroll
                for (int nt = 0; nt < 8; ++nt) {
                    const uint32_t* bh3 = vh4[nt >> 1] + (nt & 1) * 2;
                    const uint32_t* bl3 = vl4[nt >> 1] + (nt & 1) * 2;
                    mma_bf16(acc_o[nt], pah, bh3[0], bh3[1]);
                    mma_bf16(acc_o[nt], pah, bl3[0], bl3[1]);
                    mma_bf16(acc_o[nt], pal, bh3[0], bh3[1]);
                }
            }
        }
    }

#pragma unroll
    for (int h2 = 0; h2 < 2; ++h2) {
        float l = h2 ? ls1 : ls0;
        l += __shfl_xor_sync(0xffffffffu, l, 1);
        l += __shfl_xor_sync(0xffffffffu, l, 2);
        float inv = 1.0f / l;
        int tok = b * T_SEQ + qt * 128 + warp * 16 + h2 * 8 + (lane >> 2);
        float* dst = g_AO + ((size_t)tok * NH + h) * DH;
#pragma unroll
        for (int nt = 0; nt < 8; ++nt) {
            int d = nt * 8 + (lane & 3) * 2;
            float2 v;
            v.x = tf32_rna(acc_o[nt][h2 * 2 + 0] * inv);
            v.y = tf32_rna(acc_o[nt][h2 * 2 + 1] * inv);
            *(float2*)(dst + d) = v;
        }
    }
}

// ---------------------------------------------------------------------------
// Launch
// ---------------------------------------------------------------------------
extern "C" void kernel_launch(void* const* d_in, const int* in_sizes, int n_in,
                              void* d_out, int out_size)
{
    (void)in_sizes; (void)n_in; (void)out_size;
    const float* x     = (const float*)d_in[0];
    const float* w_qkv = (const float*)d_in[1];
    const float* w_o   = (const float*)d_in[2];

    float* out  = (float*)d_out;
    float* kout = out  + (size_t)M_TOK * DM;
    float* vout = kout + (size_t)M_TOK * DM;

    float *aoptr, *xr, *wqkvr, *wor;
    uint32_t *qh, *ql, *kh, *kl;
    cudaGetSymbolAddress((void**)&aoptr, g_AO);
    cudaGetSymbolAddress((void**)&xr,    g_Xr);
    cudaGetSymbolAddress((void**)&wqkvr, g_Wqkv);
    cudaGetSymbolAddress((void**)&wor,   g_Wo);
    cudaGetSymbolAddress((void**)&qh,    g_Qh);
    cudaGetSymbolAddress((void**)&ql,    g_Ql);
    cudaGetSymbolAddress((void**)&kh,    g_Kh);
    cudaGetSymbolAddress((void**)&kl,    g_Kl);

    cudaFuncSetAttribute(gemm_mma, cudaFuncAttributeMaxDynamicSharedMemorySize,
                         GEMM_DYN_SMEM);
    cudaFuncSetAttribute(attn_tc, cudaFuncAttributeMaxDynamicSharedMemorySize,
                         ATTN_DYN_SMEM);

    // tf32-RN rounding of all inputs, one launch
    round_all_kernel<<<(N4_TOT + 255) / 256, 256>>>(
        (const float4*)x, (float4*)xr,
        (const float4*)w_qkv, (float4*)wqkvr,
        (const float4*)w_o, (float4*)wor);

    // 1) QKV projection (fused epilogue): q -> bf16 planes, k -> kout + planes,
    //    v -> vout
    gemm_mma<<<dim3(3 * DM / 128, M_TOK / 128), 256, GEMM_DYN_SMEM>>>(
        xr, wqkvr, out /*dummy, unwritten*/, kout, vout, qh, ql, kh, kl,
        DM / 32, 1);

    // 2) V transpose + split
    transpose_v<<<dim3(T_SEQ / 32, DH / 32, B_SZ * NH), dim3(32, 8)>>>(vout);

    // 3) bf16x2-split tensor-core causal attention
    attn_tc<<<dim3(T_SEQ / 128, B_SZ * NH), 256, ATTN_DYN_SMEM>>>();

    // 4) output projection
    gemm_mma<<<dim3(DM / 128, M_TOK / 128), 256, GEMM_DYN_SMEM>>>(
        aoptr, wor, out, out, out, qh, ql, kh, kl, DM / 32, 0);
}

// round 16
// speedup vs baseline: 1.1479x; 1.0866x over previous
#include <cuda_runtime.h>
#include <cuda_bf16.h>
#include <cstdint>

#define B_SZ   2
#define T_SEQ  2048
#define NH     16
#define DH     64
#define DM     1024
#define M_TOK  (B_SZ * T_SEQ)   // 4096

// ---------------------------------------------------------------------------
// Scratch (__device__ globals: allocation-free rule)
// ---------------------------------------------------------------------------
__device__ float g_AO  [M_TOK * DM];     // attention output (tf32-RN rounded)
__device__ float g_Q   [M_TOK * DM];     // Q (fp32, tf32-product values)
__device__ float g_Xr  [M_TOK * DM];     // x, tf32-RN rounded
__device__ float g_Wqkv[3 * DM * DM];    // w_qkv, tf32-RN rounded
__device__ float g_Wo  [DM * DM];        // w_o, tf32-RN rounded
__device__ __nv_bfloat16 g_Vth[B_SZ * NH * DH * T_SEQ];   // V^T hi [bh][d][T]
__device__ __nv_bfloat16 g_Vtl[B_SZ * NH * DH * T_SEQ];   // V^T lo

// ---------------------------------------------------------------------------
// helpers
// ---------------------------------------------------------------------------
__device__ __forceinline__ float tf32_rna(float x) {
    uint32_t u;
    asm("cvt.rna.tf32.f32 %0, %1;" : "=r"(u) : "f"(x));
    return __uint_as_float(u);
}
__device__ __forceinline__ uint32_t pk2(float e0, float e1) {
    uint32_t d;
    asm("cvt.rn.bf16x2.f32 %0, %1, %2;" : "=r"(d) : "f"(e1), "f"(e0));
    return d;
}
__device__ __forceinline__ float bflo(uint32_t p) { return __uint_as_float(p << 16); }
__device__ __forceinline__ float bfhi(uint32_t p) { return __uint_as_float(p & 0xffff0000u); }

// Fused tf32-RN rounding of all three fp32 GEMM inputs in ONE launch.
#define N4_X  (M_TOK * DM / 4)
#define N4_WQ (3 * DM * DM / 4)
#define N4_WO (DM * DM / 4)
#define N4_TOT (N4_X + N4_WQ + N4_WO)

__global__ __launch_bounds__(256) void round_all_kernel(
    const float4* __restrict__ x,  float4* __restrict__ xr,
    const float4* __restrict__ wq, float4* __restrict__ wqr,
    const float4* __restrict__ wo, float4* __restrict__ wor)
{
    int i = blockIdx.x * blockDim.x + threadIdx.x;
    const float4* src;
    float4* dst;
    int off;
    if (i < N4_X)               { src = x;  dst = xr;  off = i; }
    else if (i < N4_X + N4_WQ)  { src = wq; dst = wqr; off = i - N4_X; }
    else if (i < N4_TOT)        { src = wo; dst = wor; off = i - N4_X - N4_WQ; }
    else return;
    float4 v = src[off];
    v.x = tf32_rna(v.x); v.y = tf32_rna(v.y);
    v.z = tf32_rna(v.z); v.w = tf32_rna(v.w);
    dst[off] = v;
}

// ---------------------------------------------------------------------------
// PTX wrappers
// ---------------------------------------------------------------------------
#define SW128(x) ((x) ^ (((x) >> 3) & 0x70))

__device__ __forceinline__ uint32_t s2u(const void* p) {
    uint32_t a;
    asm("{ .reg .u64 t; cvta.to.shared.u64 t, %1; cvt.u32.u64 %0, t; }"
        : "=r"(a) : "l"(p));
    return a;
}
__device__ __forceinline__ void ldsm_x4(
    uint32_t& r0, uint32_t& r1, uint32_t& r2, uint32_t& r3, uint32_t addr)
{
    asm volatile("ldmatrix.sync.aligned.m8n8.x4.shared.b16 {%0,%1,%2,%3}, [%4];"
                 : "=r"(r0), "=r"(r1), "=r"(r2), "=r"(r3) : "r"(addr));
}
__device__ __forceinline__ void mma_tf32(
    float* d, const uint32_t* a, uint32_t b0, uint32_t b1)
{
    asm volatile(
        "mma.sync.aligned.m16n8k8.row.col.f32.tf32.tf32.f32 "
        "{%0,%1,%2,%3}, {%4,%5,%6,%7}, {%8,%9}, {%0,%1,%2,%3};"
        : "+f"(d[0]), "+f"(d[1]), "+f"(d[2]), "+f"(d[3])
        : "r"(a[0]), "r"(a[1]), "r"(a[2]), "r"(a[3]), "r"(b0), "r"(b1));
}
__device__ __forceinline__ void mma_bf16(
    float* d, const uint32_t* a, uint32_t b0, uint32_t b1)
{
    asm volatile(
        "mma.sync.aligned.m16n8k16.row.col.f32.bf16.bf16.f32 "
        "{%0,%1,%2,%3}, {%4,%5,%6,%7}, {%8,%9}, {%0,%1,%2,%3};"
        : "+f"(d[0]), "+f"(d[1]), "+f"(d[2]), "+f"(d[3])
        : "r"(a[0]), "r"(a[1]), "r"(a[2]), "r"(a[3]), "r"(b0), "r"(b1));
}
__device__ __forceinline__ void cpa16(uint32_t dst, const void* src) {
    asm volatile("cp.async.cg.shared.global [%0], [%1], 16;"
                 :: "r"(dst), "l"(src));
}

// ---------------------------------------------------------------------------
// mma.sync tf32 NT GEMM, 2 CTAs/SM, one barrier per chunk. Plain fp32
// epilogue; output columns routed per 1024-wide segment (C0|C1|C2).
// ---------------------------------------------------------------------------
#define STAGE_BYTES 32768
#define GEMM_DYN_SMEM (3 * STAGE_BYTES)

__global__ __launch_bounds__(256, 2) void gemm_mma(
    const float* __restrict__ A, const float* __restrict__ Bm,
    float* __restrict__ C0, float* __restrict__ C1, float* __restrict__ C2,
    int nchunk)
{
    extern __shared__ char dsm[];
    const uint32_t smem0 = s2u(dsm);

    const int tid  = threadIdx.x;
    const int wid  = tid >> 5;
    const int lane = tid & 31;

    const int bm = blockIdx.y * 128;
    const int bn = blockIdx.x * 128;
    const int seg = bn >> 10;
    float* C = (seg == 0) ? C0 : ((seg == 1) ? C1 : C2);
    const int cn = bn & 1023;

    const int lr = tid >> 1;
    const int lb = (tid & 1) * 64;
    const float* gA = A  + (size_t)(bm + lr) * DM + (lb >> 2);
    const float* gB = Bm + (size_t)(bn + lr) * DM + (lb >> 2);

    const int wm = (wid >> 1) * 32;
    const int wn = (wid & 1) * 64;
    const int g  = lane >> 3;
    const int r  = lane & 7;

    uint32_t a_row[2], a_kb = (uint32_t)((g >> 1) * 16);
#pragma unroll
    for (int mt = 0; mt < 2; ++mt) {
        int row = wm + mt * 16 + (g & 1) * 8 + r;
        a_row[mt] = (uint32_t)SW128(row * 128);
    }
    uint32_t b_row[4], b_kb = (uint32_t)((g & 1) * 16);
#pragma unroll
    for (int p = 0; p < 4; ++p) {
        int row = wn + p * 16 + (g >> 1) * 8 + r;
        b_row[p] = (uint32_t)(16384 + SW128(row * 128));
    }

    float acc[2][8][4];
#pragma unroll
    for (int mt = 0; mt < 2; ++mt)
#pragma unroll
        for (int nt = 0; nt < 8; ++nt)
#pragma unroll
            for (int q = 0; q < 4; ++q) acc[mt][nt][q] = 0.0f;

    auto issue = [&](int c) {
        uint32_t sb = smem0 + (uint32_t)(c % 3) * STAGE_BYTES;
        const float* sa = gA + c * 32;
        const float* sbp = gB + c * 32;
#pragma unroll
        for (int i = 0; i < 4; ++i) {
            cpa16(sb + SW128(lr * 128 + lb + i * 16), sa + i * 4);
            cpa16(sb + 16384 + SW128(lr * 128 + lb + i * 16), sbp + i * 4);
        }
    };

    issue(0); asm volatile("cp.async.commit_group;" ::: "memory");
    if (nchunk > 1) issue(1);
    asm volatile("cp.async.commit_group;" ::: "memory");

    for (int c = 0; c < nchunk; ++c) {
        asm volatile("cp.async.wait_group 1;" ::: "memory");
        __syncthreads();
        if (c + 2 < nchunk) issue(c + 2);
        asm volatile("cp.async.commit_group;" ::: "memory");

        const uint32_t st = smem0 + (uint32_t)(c % 3) * STAGE_BYTES;
#pragma unroll
        for (int ks = 0; ks < 4; ++ks) {
            const uint32_t kbase = (uint32_t)(ks * 32);
            uint32_t af[2][4];
#pragma unroll
            for (int mt = 0; mt < 2; ++mt)
                ldsm_x4(af[mt][0], af[mt][1], af[mt][2], af[mt][3],
                        (st + a_row[mt]) ^ (kbase + a_kb));
            uint32_t bq[4][4];
#pragma unroll
            for (int p = 0; p < 4; ++p)
                ldsm_x4(bq[p][0], bq[p][1], bq[p][2], bq[p][3],
                        (st + b_row[p]) ^ (kbase + b_kb));
#pragma unroll
            for (int mt = 0; mt < 2; ++mt)
#pragma unroll
                for (int nt = 0; nt < 8; ++nt) {
                    const uint32_t* q = bq[nt >> 1];
                    if (nt & 1) mma_tf32(acc[mt][nt], af[mt], q[2], q[3]);
                    else        mma_tf32(acc[mt][nt], af[mt], q[0], q[1]);
                }
        }
    }

    const int erow = lane >> 2;
    const int ecol = (lane & 3) * 2;
#pragma unroll
    for (int mt = 0; mt < 2; ++mt) {
#pragma unroll
        for (int half = 0; half < 2; ++half) {
            int m = bm + wm + mt * 16 + half * 8 + erow;
            float* crow = C + (size_t)m * 1024 + cn + wn;
#pragma unroll
            for (int nt = 0; nt < 8; ++nt) {
                float2 v;
                v.x = acc[mt][nt][half * 2 + 0];
                v.y = acc[mt][nt][half * 2 + 1];
                *(float2*)(crow + nt * 8 + ecol) = v;
            }
        }
    }
}

// ---------------------------------------------------------------------------
// V transpose + bf16 split: vout [tok][h][64] -> Vth/Vtl [bh][d][T]
// ---------------------------------------------------------------------------
__global__ __launch_bounds__(256) void transpose_v(const float* __restrict__ V)
{
    __shared__ float tile[32][33];
    const int t0 = blockIdx.x * 32;
    const int d0 = blockIdx.y * 32;
    const int bh = blockIdx.z;
    const int b = bh >> 4, h = bh & 15;
    const int tx = threadIdx.x, ty = threadIdx.y;

#pragma unroll
    for (int i = 0; i < 4; ++i) {
        int t = t0 + ty + i * 8;
        tile[ty + i * 8][tx] =
            V[((size_t)(b * T_SEQ + t) * NH + h) * DH + d0 + tx];
    }
    __syncthreads();
#pragma unroll
    for (int i = 0; i < 4; ++i) {
        int d = d0 + ty + i * 8;
        float val = tile[tx][ty + i * 8];
        size_t o = ((size_t)bh * DH + d) * T_SEQ + t0 + tx;
        __nv_bfloat16 hb = __float2bfloat16_rn(val);
        g_Vth[o] = hb;
        g_Vtl[o] = __float2bfloat16_rn(val - __bfloat162float(hb));
    }
}

// ---------------------------------------------------------------------------
// Flash attention: S = Q K^T in tf32 (Q,K fp32 in smem, R7-proven loop,
// Q fragments hoisted), online softmax fp32, O += P V in bf16x3 (P split in
// registers, V^T bf16 planes). 1D LPT grid: heaviest q-tiles first.
// smem: Q 32KB fp32 | K 2x32KB fp32 | V 2x(16+16)KB bf16 = 160KB, 1 CTA/SM.
// ---------------------------------------------------------------------------
#define ATTN_DYN_SMEM (32768 + 65536 + 65536)

__global__ __launch_bounds__(256, 1) void attn_tc(const float* __restrict__ Kg)
{
    extern __shared__ char dsm[];
    const uint32_t sQ  = s2u(dsm);
    const uint32_t sK0 = sQ + 32768;
    const uint32_t sV0 = sQ + 98304;

    const int tid  = threadIdx.x;
    const int lane = tid & 31;
    const int warp = tid >> 5;
    const int bid  = (int)blockIdx.x;
    const int qt   = 15 - (bid >> 5);      // LPT: all qt=15 blocks first
    const int bh   = bid & 31;
    const int b    = bh >> 4, h = bh & 15;

    const int g = lane >> 3, r = lane & 7;

    const int krow = tid >> 1, kc = tid & 1;     // Q/K loader: row x d-half
    const int vd = tid >> 2, vp = tid & 3;       // V loader

    // ---- Q tile (fp32), once
    {
        const float* qsrc = g_Q +
            ((size_t)(b * T_SEQ + qt * 128 + krow) * NH + h) * DH + kc * 32;
        uint32_t qb = sQ + kc * 16384;
#pragma unroll
        for (int i = 0; i < 8; ++i)
            cpa16(qb + SW128(krow * 128 + i * 16), qsrc + i * 4);
    }
    auto issueKV = [&](int j, int s) {
        const float* ksrc = Kg +
            ((size_t)(b * T_SEQ + j * 128 + krow) * NH + h) * DH + kc * 32;
        uint32_t kb = sK0 + s * 32768 + kc * 16384;
#pragma unroll
        for (int i = 0; i < 8; ++i)
            cpa16(kb + SW128(krow * 128 + i * 16), ksrc + i * 4);
        size_t voff = ((size_t)bh * DH + vd) * T_SEQ + j * 128 + vp * 32;
        uint32_t vb = sV0 + s * 32768 + (vp >> 1) * 8192;
#pragma unroll
        for (int i = 0; i < 4; ++i) {
            uint32_t d = SW128(vd * 128 + (vp & 1) * 64 + i * 16);
            cpa16(vb + d,         g_Vth + voff + i * 8);
            cpa16(vb + 16384 + d, g_Vtl + voff + i * 8);
        }
    };

    issueKV(0, 0);
    asm volatile("cp.async.commit_group;" ::: "memory");

    const uint32_t aro = (uint32_t)SW128((warp * 16 + (g & 1) * 8 + r) * 128);
    const uint32_t kA  = (uint32_t)((g >> 1) * 16);
    uint32_t bro[4];
#pragma unroll
    for (int p = 0; p < 4; ++p)
        bro[p] = (uint32_t)SW128((p * 16 + (g >> 1) * 8 + r) * 128);
    const uint32_t kB = (uint32_t)((g & 1) * 16);

    float acc_o[8][4];
#pragma unroll
    for (int nt = 0; nt < 8; ++nt)
#pragma unroll
        for (int q = 0; q < 4; ++q) acc_o[nt][q] = 0.0f;
    float m0 = -1e30f, m1 = -1e30f, ls0 = 0.0f, ls1 = 0.0f;

    uint32_t qf[8][4];    // hoisted Q tf32 fragments (8 k8-steps)

    const int qrow0 = warp * 16 + (lane >> 2);

    for (int j = 0; j <= qt; ++j) {
        const int s = j & 1;
        asm volatile("cp.async.wait_group 0;" ::: "memory");
        __syncthreads();
        if (j < qt) {
            issueKV(j + 1, s ^ 1);
            asm volatile("cp.async.commit_group;" ::: "memory");
        }

        if (j == 0) {
#pragma unroll
            for (int ks = 0; ks < 8; ++ks) {
                const uint32_t kb8 = (uint32_t)((ks & 3) * 32);
                ldsm_x4(qf[ks][0], qf[ks][1], qf[ks][2], qf[ks][3],
                        sQ + (ks >> 2) * 16384 + (aro ^ (kb8 + kA)));
            }
        }

        const bool diag = (j == qt);
#pragma unroll
        for (int hb2 = 0; hb2 < 2; ++hb2) {
            if (diag && hb2 == 1 && warp < 4) continue;

            // ---- S = Q K^T (tf32, k8 x 8 steps)
            float acc_s[8][4];
#pragma unroll
            for (int nt = 0; nt < 8; ++nt)
#pragma unroll
                for (int q = 0; q < 4; ++q) acc_s[nt][q] = 0.0f;

#pragma unroll
            for (int ks = 0; ks < 8; ++ks) {
                const uint32_t kb8 = (uint32_t)((ks & 3) * 32);
                const uint32_t kbb = sK0 + s * 32768 + (ks >> 2) * 16384 + hb2 * 8192;
                const uint32_t kx = kb8 + kB;
                uint32_t bq[4][4];
#pragma unroll
                for (int p = 0; p < 4; ++p)
                    ldsm_x4(bq[p][0], bq[p][1], bq[p][2], bq[p][3],
                            kbb + (bro[p] ^ kx));
#pragma unroll
                for (int nt = 0; nt < 8; ++nt) {
                    const uint32_t* q = bq[nt >> 1];
                    if (nt & 1) mma_tf32(acc_s[nt], qf[ks], q[2], q[3]);
                    else        mma_tf32(acc_s[nt], qf[ks], q[0], q[1]);
                }
            }

            // ---- online softmax
#pragma unroll
            for (int h2 = 0; h2 < 2; ++h2) {
                const int qg = qrow0 + h2 * 8;
                float mx = -1e30f;
#pragma unroll
                for (int t = 0; t < 8; ++t)
#pragma unroll
                    for (int e = 0; e < 2; ++e) {
                        float sv = acc_s[t][h2 * 2 + e] * 0.125f;
                        if (diag) {
                            int kvl = hb2 * 64 + t * 8 + (lane & 3) * 2 + e;
                            if (kvl > qg) sv = -1e30f;
                        }
                        acc_s[t][h2 * 2 + e] = sv;
                        mx = fmaxf(mx, sv);
                    }
                mx = fmaxf(mx, __shfl_xor_sync(0xffffffffu, mx, 1));
                mx = fmaxf(mx, __shfl_xor_sync(0xffffffffu, mx, 2));
                float mold = h2 ? m1 : m0;
                float mn   = fmaxf(mold, mx);
                float corr = __expf(mold - mn);
                float lp   = 0.0f;
#pragma unroll
                for (int t = 0; t < 8; ++t)
#pragma unroll
                    for (int e = 0; e < 2; ++e) {
                        float p = __expf(acc_s[t][h2 * 2 + e] - mn);
                        acc_s[t][h2 * 2 + e] = p;
                        lp += p;
                    }
                if (h2) { m1 = mn; ls1 = ls1 * corr + lp; }
                else    { m0 = mn; ls0 = ls0 * corr + lp; }
#pragma unroll
                for (int nt = 0; nt < 8; ++nt) {
                    acc_o[nt][h2 * 2 + 0] *= corr;
                    acc_o[nt][h2 * 2 + 1] *= corr;
                }
            }

            // ---- O += P V (bf16x3: Ph*Vh + Ph*Vl + Pl*Vh)
            const uint32_t vbH = sV0 + s * 32768 + hb2 * 8192;
            const uint32_t vbL = vbH + 16384;
#pragma unroll
            for (int kk = 0; kk < 4; ++kk) {
                uint32_t pah[4], pal[4];
#pragma unroll
                for (int q2 = 0; q2 < 2; ++q2) {
                    const float* cs = acc_s[2 * kk + q2];
                    uint32_t h0 = pk2(cs[0], cs[1]);
                    uint32_t h1 = pk2(cs[2], cs[3]);
                    pah[q2 * 2 + 0] = h0; pah[q2 * 2 + 1] = h1;
                    pal[q2 * 2 + 0] = pk2(cs[0] - bflo(h0), cs[1] - bfhi(h0));
                    pal[q2 * 2 + 1] = pk2(cs[2] - bflo(h1), cs[3] - bfhi(h1));
                }
                const uint32_t kx = (uint32_t)(kk * 32);
                uint32_t vh4[4][4], vl4[4][4];
#pragma unroll
                for (int p = 0; p < 4; ++p) {
                    ldsm_x4(vh4[p][0], vh4[p][1], vh4[p][2], vh4[p][3],
                            vbH + (bro[p] ^ (kx + kB)));
                    ldsm_x4(vl4[p][0], vl4[p][1], vl4[p][2], vl4[p][3],
                            vbL + (bro[p] ^ (kx + kB)));
                }
#pragma unroll
                for (int nt = 0; nt < 8; ++nt) {
                    const uint32_t* bh3 = vh4[nt >> 1] + (nt & 1) * 2;
                    const uint32_t* bl3 = vl4[nt >> 1] + (nt & 1) * 2;
                    mma_bf16(acc_o[nt], pah, bh3[0], bh3[1]);
                    mma_bf16(acc_o[nt], pah, bl3[0], bl3[1]);
                    mma_bf16(acc_o[nt], pal, bh3[0], bh3[1]);
                }
            }
        }
    }

#pragma unroll
    for (int h2 = 0; h2 < 2; ++h2) {
        float l = h2 ? ls1 : ls0;
        l += __shfl_xor_sync(0xffffffffu, l, 1);
        l += __shfl_xor_sync(0xffffffffu, l, 2);
        float inv = 1.0f / l;
        int tok = b * T_SEQ + qt * 128 + warp * 16 + h2 * 8 + (lane >> 2);
        float* dst = g_AO + ((size_t)tok * NH + h) * DH;
#pragma unroll
        for (int nt = 0; nt < 8; ++nt) {
            int d = nt * 8 + (lane & 3) * 2;
            float2 v;
            v.x = tf32_rna(acc_o[nt][h2 * 2 + 0] * inv);
            v.y = tf32_rna(acc_o[nt][h2 * 2 + 1] * inv);
            *(float2*)(dst + d) = v;
        }
    }
}

// ---------------------------------------------------------------------------
// Launch
// ---------------------------------------------------------------------------
extern "C" void kernel_launch(void* const* d_in, const int* in_sizes, int n_in,
                              void* d_out, int out_size)
{
    (void)in_sizes; (void)n_in; (void)out_size;
    const float* x     = (const float*)d_in[0];
    const float* w_qkv = (const float*)d_in[1];
    const float* w_o   = (const float*)d_in[2];

    float* out  = (float*)d_out;
    float* kout = out  + (size_t)M_TOK * DM;
    float* vout = kout + (size_t)M_TOK * DM;

    float *aoptr, *qptr, *xr, *wqkvr, *wor;
    cudaGetSymbolAddress((void**)&aoptr, g_AO);
    cudaGetSymbolAddress((void**)&qptr,  g_Q);
    cudaGetSymbolAddress((void**)&xr,    g_Xr);
    cudaGetSymbolAddress((void**)&wqkvr, g_Wqkv);
    cudaGetSymbolAddress((void**)&wor,   g_Wo);

    cudaFuncSetAttribute(gemm_mma, cudaFuncAttributeMaxDynamicSharedMemorySize,
                         GEMM_DYN_SMEM);
    cudaFuncSetAttribute(attn_tc, cudaFuncAttributeMaxDynamicSharedMemorySize,
                         ATTN_DYN_SMEM);

    // tf32-RN rounding of all inputs, one launch
    round_all_kernel<<<(N4_TOT + 255) / 256, 256>>>(
        (const float4*)x, (float4*)xr,
        (const float4*)w_qkv, (float4*)wqkvr,
        (const float4*)w_o, (float4*)wor);

    // 1) QKV projection: q -> g_Q, k -> kout, v -> vout (plain fp32 epilogue)
    gemm_mma<<<dim3(3 * DM / 128, M_TOK / 128), 256, GEMM_DYN_SMEM>>>(
        xr, wqkvr, qptr, kout, vout, DM / 32);

    // 2) V transpose + bf16 split
    transpose_v<<<dim3(T_SEQ / 32, DH / 32, B_SZ * NH), dim3(32, 8)>>>(vout);

    // 3) attention: tf32 S + bf16x3 PV, LPT 1D grid
    attn_tc<<<512, 256, ATTN_DYN_SMEM>>>(kout);

    // 4) output projection
    gemm_mma<<<dim3(DM / 128, M_TOK / 128), 256, GEMM_DYN_SMEM>>>(
        aoptr, wor, out, out, out, DM / 32);
}

// round 17
// speedup vs baseline: 1.1516x; 1.0032x over previous
#include <cuda_runtime.h>
#include <cuda_bf16.h>
#include <cstdint>

#define B_SZ   2
#define T_SEQ  2048
#define NH     16
#define DH     64
#define DM     1024
#define M_TOK  (B_SZ * T_SEQ)   // 4096

// ---------------------------------------------------------------------------
// Scratch (__device__ globals: allocation-free rule)
// ---------------------------------------------------------------------------
__device__ float g_AO  [M_TOK * DM];     // attention output (tf32-RN rounded)
__device__ float g_Q   [M_TOK * DM];     // Q*0.125 (fp32)
__device__ float g_Xr  [M_TOK * DM];     // x, tf32-RN rounded
__device__ float g_Wqkv[3 * DM * DM];    // w_qkv, tf32-RN rounded
__device__ float g_Wo  [DM * DM];        // w_o, tf32-RN rounded
__device__ __nv_bfloat16 g_Vth[B_SZ * NH * DH * T_SEQ];   // V^T hi [bh][d][T]
__device__ __nv_bfloat16 g_Vtl[B_SZ * NH * DH * T_SEQ];   // V^T lo

// ---------------------------------------------------------------------------
// helpers
// ---------------------------------------------------------------------------
__device__ __forceinline__ float tf32_rna(float x) {
    uint32_t u;
    asm("cvt.rna.tf32.f32 %0, %1;" : "=r"(u) : "f"(x));
    return __uint_as_float(u);
}
__device__ __forceinline__ uint32_t pk2(float e0, float e1) {
    uint32_t d;
    asm("cvt.rn.bf16x2.f32 %0, %1, %2;" : "=r"(d) : "f"(e1), "f"(e0));
    return d;
}
__device__ __forceinline__ float bflo(uint32_t p) { return __uint_as_float(p << 16); }
__device__ __forceinline__ float bfhi(uint32_t p) { return __uint_as_float(p & 0xffff0000u); }

// Fused tf32-RN rounding of all three fp32 GEMM inputs in ONE launch.
#define N4_X  (M_TOK * DM / 4)
#define N4_WQ (3 * DM * DM / 4)
#define N4_WO (DM * DM / 4)
#define N4_TOT (N4_X + N4_WQ + N4_WO)

__global__ __launch_bounds__(256) void round_all_kernel(
    const float4* __restrict__ x,  float4* __restrict__ xr,
    const float4* __restrict__ wq, float4* __restrict__ wqr,
    const float4* __restrict__ wo, float4* __restrict__ wor)
{
    int i = blockIdx.x * blockDim.x + threadIdx.x;
    const float4* src;
    float4* dst;
    int off;
    if (i < N4_X)               { src = x;  dst = xr;  off = i; }
    else if (i < N4_X + N4_WQ)  { src = wq; dst = wqr; off = i - N4_X; }
    else if (i < N4_TOT)        { src = wo; dst = wor; off = i - N4_X - N4_WQ; }
    else return;
    float4 v = src[off];
    v.x = tf32_rna(v.x); v.y = tf32_rna(v.y);
    v.z = tf32_rna(v.z); v.w = tf32_rna(v.w);
    dst[off] = v;
}

// ---------------------------------------------------------------------------
// PTX wrappers
// ---------------------------------------------------------------------------
#define SW128(x) ((x) ^ (((x) >> 3) & 0x70))

__device__ __forceinline__ uint32_t s2u(const void* p) {
    uint32_t a;
    asm("{ .reg .u64 t; cvta.to.shared.u64 t, %1; cvt.u32.u64 %0, t; }"
        : "=r"(a) : "l"(p));
    return a;
}
__device__ __forceinline__ void ldsm_x4(
    uint32_t& r0, uint32_t& r1, uint32_t& r2, uint32_t& r3, uint32_t addr)
{
    asm volatile("ldmatrix.sync.aligned.m8n8.x4.shared.b16 {%0,%1,%2,%3}, [%4];"
                 : "=r"(r0), "=r"(r1), "=r"(r2), "=r"(r3) : "r"(addr));
}
__device__ __forceinline__ void mma_tf32(
    float* d, const uint32_t* a, uint32_t b0, uint32_t b1)
{
    asm volatile(
        "mma.sync.aligned.m16n8k8.row.col.f32.tf32.tf32.f32 "
        "{%0,%1,%2,%3}, {%4,%5,%6,%7}, {%8,%9}, {%0,%1,%2,%3};"
        : "+f"(d[0]), "+f"(d[1]), "+f"(d[2]), "+f"(d[3])
        : "r"(a[0]), "r"(a[1]), "r"(a[2]), "r"(a[3]), "r"(b0), "r"(b1));
}
__device__ __forceinline__ void mma_bf16(
    float* d, const uint32_t* a, uint32_t b0, uint32_t b1)
{
    asm volatile(
        "mma.sync.aligned.m16n8k16.row.col.f32.bf16.bf16.f32 "
        "{%0,%1,%2,%3}, {%4,%5,%6,%7}, {%8,%9}, {%0,%1,%2,%3};"
        : "+f"(d[0]), "+f"(d[1]), "+f"(d[2]), "+f"(d[3])
        : "r"(a[0]), "r"(a[1]), "r"(a[2]), "r"(a[3]), "r"(b0), "r"(b1));
}
__device__ __forceinline__ void cpa16(uint32_t dst, const void* src) {
    asm volatile("cp.async.cg.shared.global [%0], [%1], 16;"
                 :: "r"(dst), "l"(src));
}

// ---------------------------------------------------------------------------
// mma.sync tf32 NT GEMM, 2 CTAs/SM, one barrier per chunk. Per-p interleaved
// B-fragment loads (short register lifetimes). mode 1 = QKV (seg0 output
// scaled by 0.125, exact), mode 0 = plain.
// ---------------------------------------------------------------------------
#define STAGE_BYTES 32768
#define GEMM_DYN_SMEM (3 * STAGE_BYTES)

__global__ __launch_bounds__(256, 2) void gemm_mma(
    const float* __restrict__ A, const float* __restrict__ Bm,
    float* __restrict__ C0, float* __restrict__ C1, float* __restrict__ C2,
    int nchunk, int mode)
{
    extern __shared__ char dsm[];
    const uint32_t smem0 = s2u(dsm);

    const int tid  = threadIdx.x;
    const int wid  = tid >> 5;
    const int lane = tid & 31;

    const int bm = blockIdx.y * 128;
    const int bn = blockIdx.x * 128;
    const int seg = bn >> 10;
    float* C = (seg == 0) ? C0 : ((seg == 1) ? C1 : C2);
    const int cn = bn & 1023;

    const int lr = tid >> 1;
    const int lb = (tid & 1) * 64;
    const float* gA = A  + (size_t)(bm + lr) * DM + (lb >> 2);
    const float* gB = Bm + (size_t)(bn + lr) * DM + (lb >> 2);

    const int wm = (wid >> 1) * 32;
    const int wn = (wid & 1) * 64;
    const int g  = lane >> 3;
    const int r  = lane & 7;

    uint32_t a_row[2], a_kb = (uint32_t)((g >> 1) * 16);
#pragma unroll
    for (int mt = 0; mt < 2; ++mt) {
        int row = wm + mt * 16 + (g & 1) * 8 + r;
        a_row[mt] = (uint32_t)SW128(row * 128);
    }
    uint32_t b_row[4], b_kb = (uint32_t)((g & 1) * 16);
#pragma unroll
    for (int p = 0; p < 4; ++p) {
        int row = wn + p * 16 + (g >> 1) * 8 + r;
        b_row[p] = (uint32_t)(16384 + SW128(row * 128));
    }

    float acc[2][8][4];
#pragma unroll
    for (int mt = 0; mt < 2; ++mt)
#pragma unroll
        for (int nt = 0; nt < 8; ++nt)
#pragma unroll
            for (int q = 0; q < 4; ++q) acc[mt][nt][q] = 0.0f;

    auto issue = [&](int c) {
        uint32_t sb = smem0 + (uint32_t)(c % 3) * STAGE_BYTES;
        const float* sa = gA + c * 32;
        const float* sbp = gB + c * 32;
#pragma unroll
        for (int i = 0; i < 4; ++i) {
            cpa16(sb + SW128(lr * 128 + lb + i * 16), sa + i * 4);
            cpa16(sb + 16384 + SW128(lr * 128 + lb + i * 16), sbp + i * 4);
        }
    };

    issue(0); asm volatile("cp.async.commit_group;" ::: "memory");
    if (nchunk > 1) issue(1);
    asm volatile("cp.async.commit_group;" ::: "memory");

    for (int c = 0; c < nchunk; ++c) {
        asm volatile("cp.async.wait_group 1;" ::: "memory");
        __syncthreads();
        if (c + 2 < nchunk) issue(c + 2);
        asm volatile("cp.async.commit_group;" ::: "memory");

        const uint32_t st = smem0 + (uint32_t)(c % 3) * STAGE_BYTES;
#pragma unroll
        for (int ks = 0; ks < 4; ++ks) {
            const uint32_t kbase = (uint32_t)(ks * 32);
            uint32_t af[2][4];
#pragma unroll
            for (int mt = 0; mt < 2; ++mt)
                ldsm_x4(af[mt][0], af[mt][1], af[mt][2], af[mt][3],
                        (st + a_row[mt]) ^ (kbase + a_kb));
#pragma unroll
            for (int p = 0; p < 4; ++p) {
                uint32_t b0, b1, b2, b3;
                ldsm_x4(b0, b1, b2, b3, (st + b_row[p]) ^ (kbase + b_kb));
#pragma unroll
                for (int mt = 0; mt < 2; ++mt) {
                    mma_tf32(acc[mt][2 * p + 0], af[mt], b0, b1);
                    mma_tf32(acc[mt][2 * p + 1], af[mt], b2, b3);
                }
            }
        }
    }

    const int erow = lane >> 2;
    const int ecol = (lane & 3) * 2;
    const float esc = (mode == 1 && seg == 0) ? 0.125f : 1.0f;  // exact pow2
#pragma unroll
    for (int mt = 0; mt < 2; ++mt) {
#pragma unroll
        for (int half = 0; half < 2; ++half) {
            int m = bm + wm + mt * 16 + half * 8 + erow;
            float* crow = C + (size_t)m * 1024 + cn + wn;
#pragma unroll
            for (int nt = 0; nt < 8; ++nt) {
                float2 v;
                v.x = acc[mt][nt][half * 2 + 0] * esc;
                v.y = acc[mt][nt][half * 2 + 1] * esc;
                *(float2*)(crow + nt * 8 + ecol) = v;
            }
        }
    }
}

// ---------------------------------------------------------------------------
// V transpose + bf16 split: vout [tok][h][64] -> Vth/Vtl [bh][d][T]
// ---------------------------------------------------------------------------
__global__ __launch_bounds__(256) void transpose_v(const float* __restrict__ V)
{
    __shared__ float tile[32][33];
    const int t0 = blockIdx.x * 32;
    const int d0 = blockIdx.y * 32;
    const int bh = blockIdx.z;
    const int b = bh >> 4, h = bh & 15;
    const int tx = threadIdx.x, ty = threadIdx.y;

#pragma unroll
    for (int i = 0; i < 4; ++i) {
        int t = t0 + ty + i * 8;
        tile[ty + i * 8][tx] =
            V[((size_t)(b * T_SEQ + t) * NH + h) * DH + d0 + tx];
    }
    __syncthreads();
#pragma unroll
    for (int i = 0; i < 4; ++i) {
        int d = d0 + ty + i * 8;
        float val = tile[tx][ty + i * 8];
        size_t o = ((size_t)bh * DH + d) * T_SEQ + t0 + tx;
        __nv_bfloat16 hb = __float2bfloat16_rn(val);
        g_Vth[o] = hb;
        g_Vtl[o] = __float2bfloat16_rn(val - __bfloat162float(hb));
    }
}

// ---------------------------------------------------------------------------
// Flash attention: S = Q K^T in tf32 (Q pre-scaled by 0.125 exactly; hoisted
// Q fragments), online softmax fp32, O += P V in bf16x3. Per-p interleaved
// fragment loads (short lifetimes). 1D LPT grid, heaviest q-tiles first.
// smem: Q 32KB | K 2x32KB | V 2x(16+16)KB = 160KB, 1 CTA/SM.
// ---------------------------------------------------------------------------
#define ATTN_DYN_SMEM (32768 + 65536 + 65536)

__global__ __launch_bounds__(256, 1) void attn_tc(const float* __restrict__ Kg)
{
    extern __shared__ char dsm[];
    const uint32_t sQ  = s2u(dsm);
    const uint32_t sK0 = sQ + 32768;
    const uint32_t sV0 = sQ + 98304;

    const int tid  = threadIdx.x;
    const int lane = tid & 31;
    const int warp = tid >> 5;
    const int bid  = (int)blockIdx.x;
    const int qt   = 15 - (bid >> 5);      // LPT
    const int bh   = bid & 31;
    const int b    = bh >> 4, h = bh & 15;

    const int g = lane >> 3, r = lane & 7;

    const int krow = tid >> 1, kc = tid & 1;
    const int vd = tid >> 2, vp = tid & 3;

    // ---- Q tile (fp32, pre-scaled), once
    {
        const float* qsrc = g_Q +
            ((size_t)(b * T_SEQ + qt * 128 + krow) * NH + h) * DH + kc * 32;
        uint32_t qb = sQ + kc * 16384;
#pragma unroll
        for (int i = 0; i < 8; ++i)
            cpa16(qb + SW128(krow * 128 + i * 16), qsrc + i * 4);
    }
    auto issueKV = [&](int j, int s) {
        const float* ksrc = Kg +
            ((size_t)(b * T_SEQ + j * 128 + krow) * NH + h) * DH + kc * 32;
        uint32_t kb = sK0 + s * 32768 + kc * 16384;
#pragma unroll
        for (int i = 0; i < 8; ++i)
            cpa16(kb + SW128(krow * 128 + i * 16), ksrc + i * 4);
        size_t voff = ((size_t)bh * DH + vd) * T_SEQ + j * 128 + vp * 32;
        uint32_t vb = sV0 + s * 32768 + (vp >> 1) * 8192;
#pragma unroll
        for (int i = 0; i < 4; ++i) {
            uint32_t d = SW128(vd * 128 + (vp & 1) * 64 + i * 16);
            cpa16(vb + d,         g_Vth + voff + i * 8);
            cpa16(vb + 16384 + d, g_Vtl + voff + i * 8);
        }
    };

    issueKV(0, 0);
    asm volatile("cp.async.commit_group;" ::: "memory");

    const uint32_t aro = (uint32_t)SW128((warp * 16 + (g & 1) * 8 + r) * 128);
    const uint32_t kA  = (uint32_t)((g >> 1) * 16);
    uint32_t bro[4];
#pragma unroll
    for (int p = 0; p < 4; ++p)
        bro[p] = (uint32_t)SW128((p * 16 + (g >> 1) * 8 + r) * 128);
    const uint32_t kB = (uint32_t)((g & 1) * 16);

    float acc_o[8][4];
#pragma unroll
    for (int nt = 0; nt < 8; ++nt)
#pragma unroll
        for (int q = 0; q < 4; ++q) acc_o[nt][q] = 0.0f;
    float m0 = -1e30f, m1 = -1e30f, ls0 = 0.0f, ls1 = 0.0f;

    uint32_t qf[8][4];    // hoisted Q tf32 fragments

    const int qrow0 = warp * 16 + (lane >> 2);

    for (int j = 0; j <= qt; ++j) {
        const int s = j & 1;
        asm volatile("cp.async.wait_group 0;" ::: "memory");
        __syncthreads();
        if (j < qt) {
            issueKV(j + 1, s ^ 1);
            asm volatile("cp.async.commit_group;" ::: "memory");
        }

        if (j == 0) {
#pragma unroll
            for (int ks = 0; ks < 8; ++ks) {
                const uint32_t kb8 = (uint32_t)((ks & 3) * 32);
                ldsm_x4(qf[ks][0], qf[ks][1], qf[ks][2], qf[ks][3],
                        sQ + (ks >> 2) * 16384 + (aro ^ (kb8 + kA)));
            }
        }

        const bool diag = (j == qt);
#pragma unroll
        for (int hb2 = 0; hb2 < 2; ++hb2) {
            if (diag && hb2 == 1 && warp < 4) continue;

            // ---- S = Q K^T (tf32), per-p interleaved
            float acc_s[8][4];
#pragma unroll
            for (int nt = 0; nt < 8; ++nt)
#pragma unroll
                for (int q = 0; q < 4; ++q) acc_s[nt][q] = 0.0f;

#pragma unroll
            for (int ks = 0; ks < 8; ++ks) {
                const uint32_t kb8 = (uint32_t)((ks & 3) * 32);
                const uint32_t kbb = sK0 + s * 32768 + (ks >> 2) * 16384 + hb2 * 8192;
                const uint32_t kx = kb8 + kB;
#pragma unroll
                for (int p = 0; p < 4; ++p) {
                    uint32_t b0, b1, b2, b3;
                    ldsm_x4(b0, b1, b2, b3, kbb + (bro[p] ^ kx));
                    mma_tf32(acc_s[2 * p + 0], qf[ks], b0, b1);
                    mma_tf32(acc_s[2 * p + 1], qf[ks], b2, b3);
                }
            }

            // ---- online softmax (scale already folded into Q)
#pragma unroll
            for (int h2 = 0; h2 < 2; ++h2) {
                const int qg = qrow0 + h2 * 8;
                float mx = -1e30f;
#pragma unroll
                for (int t = 0; t < 8; ++t)
#pragma unroll
                    for (int e = 0; e < 2; ++e) {
                        float sv = acc_s[t][h2 * 2 + e];
                        if (diag) {
                            int kvl = hb2 * 64 + t * 8 + (lane & 3) * 2 + e;
                            if (kvl > qg) sv = -1e30f;
                        }
                        acc_s[t][h2 * 2 + e] = sv;
                        mx = fmaxf(mx, sv);
                    }
                mx = fmaxf(mx, __shfl_xor_sync(0xffffffffu, mx, 1));
                mx = fmaxf(mx, __shfl_xor_sync(0xffffffffu, mx, 2));
                float mold = h2 ? m1 : m0;
                float mn   = fmaxf(mold, mx);
                float corr = __expf(mold - mn);
                float lp   = 0.0f;
#pragma unroll
                for (int t = 0; t < 8; ++t)
#pragma unroll
                    for (int e = 0; e < 2; ++e) {
                        float p = __expf(acc_s[t][h2 * 2 + e] - mn);
                        acc_s[t][h2 * 2 + e] = p;
                        lp += p;
                    }
                if (h2) { m1 = mn; ls1 = ls1 * corr + lp; }
                else    { m0 = mn; ls0 = ls0 * corr + lp; }
#pragma unroll
                for (int nt = 0; nt < 8; ++nt) {
                    acc_o[nt][h2 * 2 + 0] *= corr;
                    acc_o[nt][h2 * 2 + 1] *= corr;
                }
            }

            // ---- O += P V (bf16x3), per-p interleaved
            const uint32_t vbH = sV0 + s * 32768 + hb2 * 8192;
            const uint32_t vbL = vbH + 16384;
#pragma unroll
            for (int kk = 0; kk < 4; ++kk) {
                uint32_t pah[4], pal[4];
#pragma unroll
                for (int q2 = 0; q2 < 2; ++q2) {
                    const float* cs = acc_s[2 * kk + q2];
                    uint32_t h0 = pk2(cs[0], cs[1]);
                    uint32_t h1 = pk2(cs[2], cs[3]);
                    pah[q2 * 2 + 0] = h0; pah[q2 * 2 + 1] = h1;
                    pal[q2 * 2 + 0] = pk2(cs[0] - bflo(h0), cs[1] - bfhi(h0));
                    pal[q2 * 2 + 1] = pk2(cs[2] - bflo(h1), cs[3] - bfhi(h1));
                }
                const uint32_t kx = (uint32_t)(kk * 32);
#pragma unroll
                for (int p = 0; p < 4; ++p) {
                    uint32_t vh0, vh1, vh2, vh3, vl0, vl1, vl2, vl3;
                    ldsm_x4(vh0, vh1, vh2, vh3, vbH + (bro[p] ^ (kx + kB)));
                    ldsm_x4(vl0, vl1, vl2, vl3, vbL + (bro[p] ^ (kx + kB)));
                    mma_bf16(acc_o[2 * p + 0], pah, vh0, vh1);
                    mma_bf16(acc_o[2 * p + 0], pah, vl0, vl1);
                    mma_bf16(acc_o[2 * p + 0], pal, vh0, vh1);
                    mma_bf16(acc_o[2 * p + 1], pah, vh2, vh3);
                    mma_bf16(acc_o[2 * p + 1], pah, vl2, vl3);
                    mma_bf16(acc_o[2 * p + 1], pal, vh2, vh3);
                }
            }
        }
    }

#pragma unroll
    for (int h2 = 0; h2 < 2; ++h2) {
        float l = h2 ? ls1 : ls0;
        l += __shfl_xor_sync(0xffffffffu, l, 1);
        l += __shfl_xor_sync(0xffffffffu, l, 2);
        float inv = 1.0f / l;
        int tok = b * T_SEQ + qt * 128 + warp * 16 + h2 * 8 + (lane >> 2);
        float* dst = g_AO + ((size_t)tok * NH + h) * DH;
#pragma unroll
        for (int nt = 0; nt < 8; ++nt) {
            int d = nt * 8 + (lane & 3) * 2;
            float2 v;
            v.x = tf32_rna(acc_o[nt][h2 * 2 + 0] * inv);
            v.y = tf32_rna(acc_o[nt][h2 * 2 + 1] * inv);
            *(float2*)(dst + d) = v;
        }
    }
}

// ---------------------------------------------------------------------------
// Launch
// ---------------------------------------------------------------------------
extern "C" void kernel_launch(void* const* d_in, const int* in_sizes, int n_in,
                              void* d_out, int out_size)
{
    (void)in_sizes; (void)n_in; (void)out_size;
    const float* x     = (const float*)d_in[0];
    const float* w_qkv = (const float*)d_in[1];
    const float* w_o   = (const float*)d_in[2];

    float* out  = (float*)d_out;
    float* kout = out  + (size_t)M_TOK * DM;
    float* vout = kout + (size_t)M_TOK * DM;

    float *aoptr, *qptr, *xr, *wqkvr, *wor;
    cudaGetSymbolAddress((void**)&aoptr, g_AO);
    cudaGetSymbolAddress((void**)&qptr,  g_Q);
    cudaGetSymbolAddress((void**)&xr,    g_Xr);
    cudaGetSymbolAddress((void**)&wqkvr, g_Wqkv);
    cudaGetSymbolAddress((void**)&wor,   g_Wo);

    cudaFuncSetAttribute(gemm_mma, cudaFuncAttributeMaxDynamicSharedMemorySize,
                         GEMM_DYN_SMEM);
    cudaFuncSetAttribute(attn_tc, cudaFuncAttributeMaxDynamicSharedMemorySize,
                         ATTN_DYN_SMEM);

    // tf32-RN rounding of all inputs, one launch
    round_all_kernel<<<(N4_TOT + 255) / 256, 256>>>(
        (const float4*)x, (float4*)xr,
        (const float4*)w_qkv, (float4*)wqkvr,
        (const float4*)w_o, (float4*)wor);

    // 1) QKV projection: q*0.125 -> g_Q, k -> kout, v -> vout
    gemm_mma<<<dim3(3 * DM / 128, M_TOK / 128), 256, GEMM_DYN_SMEM>>>(
        xr, wqkvr, qptr, kout, vout, DM / 32, 1);

    // 2) V transpose + bf16 split
    transpose_v<<<dim3(T_SEQ / 32, DH / 32, B_SZ * NH), dim3(32, 8)>>>(vout);

    // 3) attention: tf32 S + bf16x3 PV, LPT 1D grid
    attn_tc<<<512, 256, ATTN_DYN_SMEM>>>(kout);

    // 4) output projection
    gemm_mma<<<dim3(DM / 128, M_TOK / 128), 256, GEMM_DYN_SMEM>>>(
        aoptr, wor, out, out, out, DM / 32, 0);
}